// round 16
// baseline (speedup 1.0000x reference)
#include <cuda_runtime.h>
#include <math.h>

#define NB    8
#define NPTS  4096
#define PAD   32                     // sentinel entries each side (covers frozen-lane reach 32)
#define NTOT  (NPTS + 2 * PAD)       // 4160
#define BT    256                    // knn block threads: 8 warps = 64 points
#define INF_F __int_as_float(0x7f800000)

// ---- scratch (device globals; no allocations allowed) ----
__device__ float  g_std24[24];
__device__ float  g_scal[8];                 // S1,1/S1,blend,Q1,cos(d1),sin(d1),d1
__device__ float  g_lstd[NB * NPTS * 3];
__device__ float  g_curv[NB * NPTS];
__device__ unsigned long long g_curvsum[NB]; // fixed-point (2^40) curvature sums
__device__ float4 g_sorted[NB * NPTS];       // per batch: sorted by x; .w = orig idx bits
__device__ float4 g_sumA[NB * NPTS];         // sx, sy, sz, sxx   (sorted order)
__device__ float4 g_sumB[NB * NPTS];         // syy, szz, sxy, sxz
__device__ float  g_sumC[NB * NPTS];         // syz

// ============================================================
// Kernel 1: per-(batch,dim) std over N (ddof=1), 24 blocks
// ============================================================
__global__ void bd_std_kernel(const float* __restrict__ xyz) {
    __shared__ double ssum[256];
    __shared__ double ssq[256];
    int bd = blockIdx.x;
    const float* p = xyz + (bd / 3) * NPTS * 3 + (bd % 3);
    double s = 0.0, s2 = 0.0;
#pragma unroll
    for (int k = 0; k < NPTS / 256; k++) {
        double v = (double)p[3 * (threadIdx.x + k * 256)];
        s += v; s2 += v * v;
    }
    ssum[threadIdx.x] = s; ssq[threadIdx.x] = s2;
    __syncthreads();
    for (int off = 128; off > 0; off >>= 1) {
        if (threadIdx.x < off) {
            ssum[threadIdx.x] += ssum[threadIdx.x + off];
            ssq[threadIdx.x]  += ssq[threadIdx.x + off];
        }
        __syncthreads();
    }
    if (threadIdx.x == 0) {
        double mean = ssum[0] / NPTS;
        double var  = (ssq[0] - (double)NPTS * mean * mean) / (NPTS - 1);
        g_std24[bd] = (float)sqrt(var > 0.0 ? var : 0.0);
    }
}

// ============================================================
// Kernel 2: global scalars + zero curvsum
// ============================================================
__global__ void consts_kernel() {
    if (threadIdx.x != 0) return;
    double g = 0.0;
    for (int i = 0; i < 24; i++) g += (double)g_std24[i];
    g /= 24.0;
    double asig  = 0.3 * (1.0 + g);
    double S1    = asig + 1e-6;
    double blend = 1.0 / (1.0 + exp(-(g - 0.1) * 10.0));
    double h  = 1.0 / 22.0;
    double d1 = h / S1;
    g_scal[0] = (float)S1;
    g_scal[1] = (float)(1.0 / S1);
    g_scal[2] = (float)blend;
    g_scal[3] = (float)exp(-d1 * d1);
    g_scal[4] = (float)cos(d1);
    g_scal[5] = (float)sin(d1);
    g_scal[6] = (float)d1;
    for (int b = 0; b < NB; b++) g_curvsum[b] = 0ull;
}

// ============================================================
// Kernel 3: per-batch bitonic sort by x (u64 = flip(x)<<32 | idx)
// ============================================================
__global__ void __launch_bounds__(1024)
sort_kernel(const float* __restrict__ xyz) {
    __shared__ unsigned long long keys[NPTS];
    int b = blockIdx.x, tid = threadIdx.x;
    const float* base = xyz + (size_t)b * NPTS * 3;

    for (int e = tid; e < NPTS; e += 1024) {
        unsigned u = __float_as_uint(base[3 * e]);
        u ^= (u & 0x80000000u) ? 0xFFFFFFFFu : 0x80000000u;
        keys[e] = ((unsigned long long)u << 32) | (unsigned)e;
    }
    __syncthreads();

    for (int k = 2; k <= NPTS; k <<= 1) {
        for (int j = k >> 1; j > 0; j >>= 1) {
#pragma unroll
            for (int s = 0; s < 4; s++) {
                int e = tid + (s << 10);
                int p = e ^ j;
                if (p > e) {
                    unsigned long long a = keys[e], c = keys[p];
                    bool asc = ((e & k) == 0);
                    if ((a > c) == asc) { keys[e] = c; keys[p] = a; }
                }
            }
            __syncthreads();
        }
    }

    for (int e = tid; e < NPTS; e += 1024) {
        int idx = (int)(unsigned)(keys[e] & 0xFFFFFFFFu);
        float x = base[3 * idx], y = base[3 * idx + 1], z = base[3 * idx + 2];
        g_sorted[b * NPTS + e] = make_float4(x, y, z, __int_as_float(idx));
    }
}

// ============================================================
// Kernel 4: 4-way-split kNN, SoA smem (X/Y/Z), 49.9KB -> 4 blocks/SM,
// single wave (512 blocks <= 592 capacity). Exact f32 top-16 per lane,
// union via bitonic merge; phase-2 tau rescan; writes 9 cov sums.
// ============================================================
__global__ void __launch_bounds__(BT, 4)
knn_kernel() {
    extern __shared__ float S[];
    float* X = S;
    float* Y = S + NTOT;
    float* Z = S + 2 * NTOT;

    int b = blockIdx.y;
    int tid = threadIdx.x;
    for (int i = tid; i < NPTS; i += BT) {
        float4 v = g_sorted[b * NPTS + i];
        X[PAD + i] = v.x; Y[PAD + i] = v.y; Z[PAD + i] = v.z;
    }
    if (tid < 2 * PAD) {
        int at = (tid < PAD) ? tid : (NPTS + PAD + (tid - PAD));
        X[at] = (tid < PAD) ? -3e18f : 3e18f;
        Y[at] = 0.f; Z[at] = 0.f;
    }
    __syncthreads();

    int wi   = tid >> 5, lane = tid & 31;
    int pt   = lane & 7;                        // point within warp (adjacent!)
    int sub  = lane >> 3;                       // 0..3
    int side = sub >> 1;                        // 0 = low, 1 = high
    int par  = sub & 1;                         // scan parity
    int dir  = side ? 1 : -1;
    int spj  = blockIdx.x * 64 + wi * 8 + pt + PAD;
    float qx = X[spj], qy = Y[spj], qz = Z[spj];

    float L[16];
#pragma unroll
    for (int t = 0; t < 16; t++) L[t] = INF_F;

    int   jpos = spj + dir * (1 + par);
    float nx   = X[jpos];
    bool  done = false;

    while (__any_sync(0xffffffffu, !done)) {
        float t4 = fminf(L[15], __shfl_xor_sync(0xffffffffu, L[15], 8));
        t4 = fminf(t4, __shfl_xor_sync(0xffffffffu, t4, 16));
        float thr = fminf(t4, 1e30f);           // cap: sentinel gap (9e36) always stops
        float g   = nx - qx;                    // sign-free: compared squared
        done = done || (g * g > thr);
        bool act = !done;

        float nxn = X[jpos + dir * 16];         // prefetch next gap x (in-bounds: PAD=32)
#pragma unroll
        for (int u = 0; u < 8; u++) {
            int j = jpos + dir * 2 * u;
            float dx = qx - X[j], dy = qy - Y[j], dz = qz - Z[j];
            float d2 = fmaf(dz, dz, fmaf(dy, dy, dx * dx));
            float v  = act ? d2 : INF_F;
            if (v < L[15]) {                    // per-candidate gate
                float pv = L[0];
                L[0] = fminf(v, L[0]);
#pragma unroll
                for (int t = 1; t < 16; t++) {
                    float o = L[t];
                    L[t] = fminf(fmaxf(v, pv), o);
                    pv = o;
                }
            }
        }
        if (act) { jpos += dir * 16; nx = nxn; }
    }

    // ---- union top-16 threshold over the 4 sub-lists (exact f32) ----
    __syncwarp();
    float E[16];
#pragma unroll
    for (int i = 0; i < 16; i++) {
        float bi = __shfl_xor_sync(0xffffffffu, L[15 - i], 8);
        E[i] = fminf(L[i], bi);                 // top-16 of pair union (bitonic seq)
    }
#pragma unroll
    for (int d = 8; d >= 1; d >>= 1) {          // bitonic clean -> ascending
#pragma unroll
        for (int i = 0; i < 16; i++) {
            if ((i & d) == 0) {
                float a2 = E[i], b2 = E[i + d];
                E[i] = fminf(a2, b2); E[i + d] = fmaxf(a2, b2);
            }
        }
    }
    float tau = 0.0f;
#pragma unroll
    for (int i = 0; i < 16; i++) {
        float m = fminf(E[i], __shfl_xor_sync(0xffffffffu, E[15 - i], 16));
        tau = fmaxf(tau, m);                    // 16th smallest of 4-way union
    }

    // ---- phase 2: per-lane stride-2 rescan, centered stats ----
    float sx = 0.f, sy = 0.f, sz = 0.f;
    float sxx = 0.f, syy = 0.f, szz = 0.f, sxy = 0.f, sxz = 0.f, syz = 0.f;
    for (int j = spj + dir * (1 + par); ; j += dir * 2) {
        float dx = X[j] - qx;
        if (dx * dx > tau) break;               // sentinel x guarantees exit
        float dy = Y[j] - qy, dz = Z[j] - qz;
        float d2 = fmaf(dz, dz, fmaf(dy, dy, dx * dx));
        float f  = (d2 <= tau) ? 1.0f : 0.0f;
        dx *= f; dy *= f; dz *= f;
        sx += dx; sy += dy; sz += dz;
        sxx = fmaf(dx, dx, sxx); syy = fmaf(dy, dy, syy); szz = fmaf(dz, dz, szz);
        sxy = fmaf(dx, dy, sxy); sxz = fmaf(dx, dz, sxz); syz = fmaf(dy, dz, syz);
    }
    __syncwarp();
#pragma unroll
    for (int o = 8; o <= 16; o <<= 1) {
        sx  += __shfl_xor_sync(0xffffffffu, sx,  o);
        sy  += __shfl_xor_sync(0xffffffffu, sy,  o);
        sz  += __shfl_xor_sync(0xffffffffu, sz,  o);
        sxx += __shfl_xor_sync(0xffffffffu, sxx, o);
        syy += __shfl_xor_sync(0xffffffffu, syy, o);
        szz += __shfl_xor_sync(0xffffffffu, szz, o);
        sxy += __shfl_xor_sync(0xffffffffu, sxy, o);
        sxz += __shfl_xor_sync(0xffffffffu, sxz, o);
        syz += __shfl_xor_sync(0xffffffffu, syz, o);
    }

    if (sub == 0) {                             // 8 adjacent points -> coalesced stores
        int gi = b * NPTS + (spj - PAD);
        g_sumA[gi] = make_float4(sx, sy, sz, sxx);
        g_sumB[gi] = make_float4(syy, szz, sxy, sxz);
        g_sumC[gi] = syz;
    }
}

// ============================================================
// Kernel 5: eigen/curv/lstd from cov sums (all lanes active),
// bit-identical double math; block-reduced fixed-point curvsum.
// grid (NPTS/256, NB), 256 threads
// ============================================================
__global__ void __launch_bounds__(256)
eigen_kernel() {
    __shared__ unsigned long long wsum[8];
    int b  = blockIdx.y;
    int sp = blockIdx.x * 256 + threadIdx.x;
    int gi = b * NPTS + sp;

    float4 A = g_sumA[gi];
    float4 Bv = g_sumB[gi];
    float  syz = g_sumC[gi];

    double mx = (double)A.x / 16.0, my = (double)A.y / 16.0, mz = (double)A.z / 16.0;
    double cxx = ((double)A.w  - 16.0 * mx * mx) / 15.0;
    double cyy = ((double)Bv.x - 16.0 * my * my) / 15.0;
    double czz = ((double)Bv.y - 16.0 * mz * mz) / 15.0;
    double cxy = ((double)Bv.z - 16.0 * mx * my) / 15.0;
    double cxz = ((double)Bv.w - 16.0 * mx * mz) / 15.0;
    double cyz = ((double)syz  - 16.0 * my * mz) / 15.0;

    double tr = cxx + cyy + czz;
    double qm = tr / 3.0;
    double aa = cxx - qm, bb = cyy - qm, cc2 = czz - qm;
    double p2 = aa * aa + bb * bb + cc2 * cc2
              + 2.0 * (cxy * cxy + cxz * cxz + cyz * cyz);
    double lmin;
    if (p2 <= 1e-300) {
        lmin = qm;
    } else {
        double pp  = sqrt(p2 / 6.0);
        double inv = 1.0 / pp;
        double b00 = aa * inv, b11 = bb * inv, b22 = cc2 * inv;
        double b01 = cxy * inv, b02 = cxz * inv, b12 = cyz * inv;
        double det = b00 * (b11 * b22 - b12 * b12)
                   - b01 * (b01 * b22 - b12 * b02)
                   + b02 * (b01 * b12 - b11 * b02);
        double r = 0.5 * det;
        r = r < -1.0 ? -1.0 : (r > 1.0 ? 1.0 : r);
        double phi = acos(r) * (1.0 / 3.0);
        lmin = qm + 2.0 * pp * cos(phi + 2.0943951023931953);
    }

    double curv = lmin / (tr + 1e-6);
    int orig = __float_as_int(g_sorted[gi].w);
    int go   = b * NPTS + orig;
    g_curv[go] = (float)curv;
    g_lstd[go * 3 + 0] = (float)sqrt(cxx > 0.0 ? cxx : 0.0);
    g_lstd[go * 3 + 1] = (float)sqrt(cyy > 0.0 ? cyy : 0.0);
    g_lstd[go * 3 + 2] = (float)sqrt(czz > 0.0 ? czz : 0.0);

    // deterministic fixed-point (2^40) sum: warp -> block -> one atomic
    unsigned long long sc = (unsigned long long)llrint(curv * 1099511627776.0);
#pragma unroll
    for (int o = 16; o; o >>= 1)
        sc += __shfl_xor_sync(0xffffffffu, sc, o);
    int lane = threadIdx.x & 31, wi = threadIdx.x >> 5;
    if (lane == 0) wsum[wi] = sc;
    __syncthreads();
    if (threadIdx.x == 0) {
        unsigned long long t = 0;
        for (int w = 0; w < 8; w++) t += wsum[w];
        atomicAdd(&g_curvsum[b], t);
    }
}

// ============================================================
// Kernel 6: embedding via geometric/rotation recurrences
// ============================================================
__global__ void __launch_bounds__(96)
embed_kernel(const float* __restrict__ xyz, float* __restrict__ out) {
    __shared__ float sm[32][129];
    int tid = threadIdx.x;
    int p = tid & 31;
    int d = tid >> 5;
    int b = blockIdx.y;
    int n0 = blockIdx.x * 32;
    int gp = b * NPTS + n0 + p;

    float x    = xyz[(size_t)gp * 3 + d];
    float lstd = g_lstd[(size_t)gp * 3 + d];
    float curv = g_curv[gp];
    float cm   = (float)((double)(long long)g_curvsum[b]
                         * (1.0 / 1099511627776.0) * (1.0 / 4096.0));
    float w    = 1.0f / (1.0f + __expf(-10.0f * (curv - cm)));

    float invS1 = g_scal[1], blend = g_scal[2];
    float Q1 = g_scal[3], cd1 = g_scal[4], sd1 = g_scal[5], d1 = g_scal[6];

    float Aw = w * blend;
    float Bw = w * (1.0f - blend);
    float Cw = 1.0f - w;

    const float h   = 0.045454545454545456f;   // 1/22
    const float fv0 = -0.9545454545454546f;    // FEAT_VAL[0]

    float S2   = fmaf(0.3f, lstd, 0.3f) + 1e-6f;
    float inv2 = 1.0f / S2;
    float d2s  = h * inv2;
    float Q2   = __expf(-d2s * d2s);

    bool  up  = (x <= 0.0f);
    float sgn = up ? 1.0f : -1.0f;
    int   f   = up ? 0 : 42;
    int   df  = up ? 1 : -1;
    float fva = up ? fv0 : -fv0;

    float t1 = (x - fva) * invS1;
    float t2 = (x - fva) * inv2;
    float G1 = __expf(-0.5f * t1 * t1);
    float G2 = __expf(-0.5f * t2 * t2);
    float r1 = __expf(sgn * d1  * (t1 - sgn * 0.5f * d1));
    float r2 = __expf(sgn * d2s * (t2 - sgn * 0.5f * d2s));
    float cc = __cosf(t1);
    float sn = __sinf(t1);
    float sd = up ? sd1 : -sd1;

    for (int it = 0; it < 43; it++) {
        float val = fmaf(Aw, G1, fmaf(Bw, cc, Cw * G2));
        int col;
        if (d < 2) col = d * 43 + f;
        else       col = (f < 41) ? (86 + f) : ((f == 42) ? 127 : -1);
        if (col >= 0) sm[p][col] = val;
        G1 *= r1; r1 *= Q1;
        G2 *= r2; r2 *= Q2;
        float cn  = fmaf(cc, cd1,  sn * sd);
        float sn2 = fmaf(sn, cd1, -cc * sd);
        cc = cn; sn = sn2;
        f += df;
    }
    __syncthreads();

    float* ob = out + ((size_t)b * NPTS + n0) * 128;
    for (int i = tid; i < 32 * 128; i += 96)
        ob[i] = sm[i >> 7][i & 127];
}

// ============================================================
extern "C" void kernel_launch(void* const* d_in, const int* in_sizes, int n_in,
                              void* d_out, int out_size) {
    const float* xyz = (const float*)d_in[0];
    float* out = (float*)d_out;
    (void)in_sizes; (void)n_in; (void)out_size;

    const int knn_smem = 3 * NTOT * 4;   // 49920 B -> 4 blocks/SM
    cudaFuncSetAttribute(knn_kernel, cudaFuncAttributeMaxDynamicSharedMemorySize, knn_smem);

    bd_std_kernel<<<24, 256>>>(xyz);
    consts_kernel<<<1, 32>>>();
    sort_kernel<<<NB, 1024>>>(xyz);
    dim3 kg(NPTS / 64, NB);              // 64 x 8 = 512 blocks, single wave at 4/SM
    knn_kernel<<<kg, BT, knn_smem>>>();
    dim3 eg2(NPTS / 256, NB);
    eigen_kernel<<<eg2, 256>>>();
    dim3 eg(NPTS / 32, NB);
    embed_kernel<<<eg, 96>>>(xyz, out);
}

// round 17
// speedup vs baseline: 1.0374x; 1.0374x over previous
#include <cuda_runtime.h>
#include <math.h>

#define NB    8
#define NPTS  4096
#define PAD   32                     // sentinel entries each side (covers frozen-lane reach 32)
#define NTOT  (NPTS + 2 * PAD)       // 4160
#define BT    256                    // knn block threads: 8 warps = 64 points
#define INF_F __int_as_float(0x7f800000)

// ---- scratch (device globals; no allocations allowed) ----
__device__ float  g_std24[24];
__device__ float  g_scal[8];                 // S1,1/S1,blend,Q1,cos(d1),sin(d1),d1
__device__ float  g_lstd[NB * NPTS * 3];
__device__ float  g_curv[NB * NPTS];
__device__ unsigned long long g_curvsum[NB]; // fixed-point (2^40) curvature sums
__device__ float4 g_sorted[NB * NPTS];       // per batch: sorted by x; .w = orig idx bits
__device__ float4 g_sumA[NB * NPTS];         // sx, sy, sz, sxx   (sorted order)
__device__ float4 g_sumB[NB * NPTS];         // syy, szz, sxy, sxz
__device__ float  g_sumC[NB * NPTS];         // syz

// ============================================================
// Kernel 1: per-(batch,dim) std over N (ddof=1), 24 blocks
// ============================================================
__global__ void bd_std_kernel(const float* __restrict__ xyz) {
    __shared__ double ssum[256];
    __shared__ double ssq[256];
    int bd = blockIdx.x;
    const float* p = xyz + (bd / 3) * NPTS * 3 + (bd % 3);
    double s = 0.0, s2 = 0.0;
#pragma unroll
    for (int k = 0; k < NPTS / 256; k++) {
        double v = (double)p[3 * (threadIdx.x + k * 256)];
        s += v; s2 += v * v;
    }
    ssum[threadIdx.x] = s; ssq[threadIdx.x] = s2;
    __syncthreads();
    for (int off = 128; off > 0; off >>= 1) {
        if (threadIdx.x < off) {
            ssum[threadIdx.x] += ssum[threadIdx.x + off];
            ssq[threadIdx.x]  += ssq[threadIdx.x + off];
        }
        __syncthreads();
    }
    if (threadIdx.x == 0) {
        double mean = ssum[0] / NPTS;
        double var  = (ssq[0] - (double)NPTS * mean * mean) / (NPTS - 1);
        g_std24[bd] = (float)sqrt(var > 0.0 ? var : 0.0);
    }
}

// ============================================================
// Kernel 2: global scalars + zero curvsum
// ============================================================
__global__ void consts_kernel() {
    if (threadIdx.x != 0) return;
    double g = 0.0;
    for (int i = 0; i < 24; i++) g += (double)g_std24[i];
    g /= 24.0;
    double asig  = 0.3 * (1.0 + g);
    double S1    = asig + 1e-6;
    double blend = 1.0 / (1.0 + exp(-(g - 0.1) * 10.0));
    double h  = 1.0 / 22.0;
    double d1 = h / S1;
    g_scal[0] = (float)S1;
    g_scal[1] = (float)(1.0 / S1);
    g_scal[2] = (float)blend;
    g_scal[3] = (float)exp(-d1 * d1);
    g_scal[4] = (float)cos(d1);
    g_scal[5] = (float)sin(d1);
    g_scal[6] = (float)d1;
    for (int b = 0; b < NB; b++) g_curvsum[b] = 0ull;
}

// ============================================================
// Kernel 3: per-batch bitonic sort by x (u64 = flip(x)<<32 | idx)
// ============================================================
__global__ void __launch_bounds__(1024)
sort_kernel(const float* __restrict__ xyz) {
    __shared__ unsigned long long keys[NPTS];
    int b = blockIdx.x, tid = threadIdx.x;
    const float* base = xyz + (size_t)b * NPTS * 3;

    for (int e = tid; e < NPTS; e += 1024) {
        unsigned u = __float_as_uint(base[3 * e]);
        u ^= (u & 0x80000000u) ? 0xFFFFFFFFu : 0x80000000u;
        keys[e] = ((unsigned long long)u << 32) | (unsigned)e;
    }
    __syncthreads();

    for (int k = 2; k <= NPTS; k <<= 1) {
        for (int j = k >> 1; j > 0; j >>= 1) {
#pragma unroll
            for (int s = 0; s < 4; s++) {
                int e = tid + (s << 10);
                int p = e ^ j;
                if (p > e) {
                    unsigned long long a = keys[e], c = keys[p];
                    bool asc = ((e & k) == 0);
                    if ((a > c) == asc) { keys[e] = c; keys[p] = a; }
                }
            }
            __syncthreads();
        }
    }

    for (int e = tid; e < NPTS; e += 1024) {
        int idx = (int)(unsigned)(keys[e] & 0xFFFFFFFFu);
        float x = base[3 * idx], y = base[3 * idx + 1], z = base[3 * idx + 2];
        g_sorted[b * NPTS + e] = make_float4(x, y, z, __int_as_float(idx));
    }
}

// ============================================================
// Kernel 4: 4-way-split kNN, SoA smem, 4 blocks/SM single wave.
// Warp-tile INTERLEAVE: warp wi of block x owns tile (x + 64*wi)
// -> every block samples 8 spread regions -> balanced block cost.
// ============================================================
__global__ void __launch_bounds__(BT, 4)
knn_kernel() {
    extern __shared__ float S[];
    float* X = S;
    float* Y = S + NTOT;
    float* Z = S + 2 * NTOT;

    int b = blockIdx.y;
    int tid = threadIdx.x;
    for (int i = tid; i < NPTS; i += BT) {
        float4 v = g_sorted[b * NPTS + i];
        X[PAD + i] = v.x; Y[PAD + i] = v.y; Z[PAD + i] = v.z;
    }
    if (tid < 2 * PAD) {
        int at = (tid < PAD) ? tid : (NPTS + PAD + (tid - PAD));
        X[at] = (tid < PAD) ? -3e18f : 3e18f;
        Y[at] = 0.f; Z[at] = 0.f;
    }
    __syncthreads();

    int wi   = tid >> 5, lane = tid & 31;
    int pt   = lane & 7;                        // point within warp (adjacent!)
    int sub  = lane >> 3;                       // 0..3
    int side = sub >> 1;                        // 0 = low, 1 = high
    int par  = sub & 1;                         // scan parity
    int dir  = side ? 1 : -1;
    int tile = blockIdx.x + (wi << 6);          // interleaved: balanced block cost
    int spj  = tile * 8 + pt + PAD;
    float qx = X[spj], qy = Y[spj], qz = Z[spj];

    float L[16];
#pragma unroll
    for (int t = 0; t < 16; t++) L[t] = INF_F;

    int   jpos = spj + dir * (1 + par);
    float nx   = X[jpos];
    bool  done = false;

    while (__any_sync(0xffffffffu, !done)) {
        float t4 = fminf(L[15], __shfl_xor_sync(0xffffffffu, L[15], 8));
        t4 = fminf(t4, __shfl_xor_sync(0xffffffffu, t4, 16));
        float thr = fminf(t4, 1e30f);           // cap: sentinel gap (9e36) always stops
        float g   = nx - qx;                    // sign-free: compared squared
        done = done || (g * g > thr);
        bool act = !done;

        float nxn = X[jpos + dir * 16];         // prefetch next gap x (in-bounds: PAD=32)
#pragma unroll
        for (int u = 0; u < 8; u++) {
            int j = jpos + dir * 2 * u;
            float dx = qx - X[j], dy = qy - Y[j], dz = qz - Z[j];
            float d2 = fmaf(dz, dz, fmaf(dy, dy, dx * dx));
            float v  = act ? d2 : INF_F;
            if (v < L[15]) {                    // per-candidate gate
                float pv = L[0];
                L[0] = fminf(v, L[0]);
#pragma unroll
                for (int t = 1; t < 16; t++) {
                    float o = L[t];
                    L[t] = fminf(fmaxf(v, pv), o);
                    pv = o;
                }
            }
        }
        if (act) { jpos += dir * 16; nx = nxn; }
    }

    // ---- union top-16 threshold over the 4 sub-lists (exact f32) ----
    __syncwarp();
    float E[16];
#pragma unroll
    for (int i = 0; i < 16; i++) {
        float bi = __shfl_xor_sync(0xffffffffu, L[15 - i], 8);
        E[i] = fminf(L[i], bi);                 // top-16 of pair union (bitonic seq)
    }
#pragma unroll
    for (int d = 8; d >= 1; d >>= 1) {          // bitonic clean -> ascending
#pragma unroll
        for (int i = 0; i < 16; i++) {
            if ((i & d) == 0) {
                float a2 = E[i], b2 = E[i + d];
                E[i] = fminf(a2, b2); E[i + d] = fmaxf(a2, b2);
            }
        }
    }
    float tau = 0.0f;
#pragma unroll
    for (int i = 0; i < 16; i++) {
        float m = fminf(E[i], __shfl_xor_sync(0xffffffffu, E[15 - i], 16));
        tau = fmaxf(tau, m);                    // 16th smallest of 4-way union
    }

    // ---- phase 2: per-lane stride-2 rescan, centered stats ----
    float sx = 0.f, sy = 0.f, sz = 0.f;
    float sxx = 0.f, syy = 0.f, szz = 0.f, sxy = 0.f, sxz = 0.f, syz = 0.f;
    for (int j = spj + dir * (1 + par); ; j += dir * 2) {
        float dx = X[j] - qx;
        if (dx * dx > tau) break;               // sentinel x guarantees exit
        float dy = Y[j] - qy, dz = Z[j] - qz;
        float d2 = fmaf(dz, dz, fmaf(dy, dy, dx * dx));
        float f  = (d2 <= tau) ? 1.0f : 0.0f;
        dx *= f; dy *= f; dz *= f;
        sx += dx; sy += dy; sz += dz;
        sxx = fmaf(dx, dx, sxx); syy = fmaf(dy, dy, syy); szz = fmaf(dz, dz, szz);
        sxy = fmaf(dx, dy, sxy); sxz = fmaf(dx, dz, sxz); syz = fmaf(dy, dz, syz);
    }
    __syncwarp();
#pragma unroll
    for (int o = 8; o <= 16; o <<= 1) {
        sx  += __shfl_xor_sync(0xffffffffu, sx,  o);
        sy  += __shfl_xor_sync(0xffffffffu, sy,  o);
        sz  += __shfl_xor_sync(0xffffffffu, sz,  o);
        sxx += __shfl_xor_sync(0xffffffffu, sxx, o);
        syy += __shfl_xor_sync(0xffffffffu, syy, o);
        szz += __shfl_xor_sync(0xffffffffu, szz, o);
        sxy += __shfl_xor_sync(0xffffffffu, sxy, o);
        sxz += __shfl_xor_sync(0xffffffffu, sxz, o);
        syz += __shfl_xor_sync(0xffffffffu, syz, o);
    }

    if (sub == 0) {                             // 8 adjacent points -> coalesced stores
        int gi = b * NPTS + (spj - PAD);
        g_sumA[gi] = make_float4(sx, sy, sz, sxx);
        g_sumB[gi] = make_float4(syy, szz, sxy, sxz);
        g_sumC[gi] = syz;
    }
}

// ============================================================
// Kernel 5: eigen/curv/lstd from cov sums (all lanes active),
// bit-identical double math; block-reduced fixed-point curvsum.
// ============================================================
__global__ void __launch_bounds__(256)
eigen_kernel() {
    __shared__ unsigned long long wsum[8];
    int b  = blockIdx.y;
    int sp = blockIdx.x * 256 + threadIdx.x;
    int gi = b * NPTS + sp;

    float4 A = g_sumA[gi];
    float4 Bv = g_sumB[gi];
    float  syz = g_sumC[gi];

    double mx = (double)A.x / 16.0, my = (double)A.y / 16.0, mz = (double)A.z / 16.0;
    double cxx = ((double)A.w  - 16.0 * mx * mx) / 15.0;
    double cyy = ((double)Bv.x - 16.0 * my * my) / 15.0;
    double czz = ((double)Bv.y - 16.0 * mz * mz) / 15.0;
    double cxy = ((double)Bv.z - 16.0 * mx * my) / 15.0;
    double cxz = ((double)Bv.w - 16.0 * mx * mz) / 15.0;
    double cyz = ((double)syz  - 16.0 * my * mz) / 15.0;

    double tr = cxx + cyy + czz;
    double qm = tr / 3.0;
    double aa = cxx - qm, bb = cyy - qm, cc2 = czz - qm;
    double p2 = aa * aa + bb * bb + cc2 * cc2
              + 2.0 * (cxy * cxy + cxz * cxz + cyz * cyz);
    double lmin;
    if (p2 <= 1e-300) {
        lmin = qm;
    } else {
        double pp  = sqrt(p2 / 6.0);
        double inv = 1.0 / pp;
        double b00 = aa * inv, b11 = bb * inv, b22 = cc2 * inv;
        double b01 = cxy * inv, b02 = cxz * inv, b12 = cyz * inv;
        double det = b00 * (b11 * b22 - b12 * b12)
                   - b01 * (b01 * b22 - b12 * b02)
                   + b02 * (b01 * b12 - b11 * b02);
        double r = 0.5 * det;
        r = r < -1.0 ? -1.0 : (r > 1.0 ? 1.0 : r);
        double phi = acos(r) * (1.0 / 3.0);
        lmin = qm + 2.0 * pp * cos(phi + 2.0943951023931953);
    }

    double curv = lmin / (tr + 1e-6);
    int orig = __float_as_int(g_sorted[gi].w);
    int go   = b * NPTS + orig;
    g_curv[go] = (float)curv;
    g_lstd[go * 3 + 0] = (float)sqrt(cxx > 0.0 ? cxx : 0.0);
    g_lstd[go * 3 + 1] = (float)sqrt(cyy > 0.0 ? cyy : 0.0);
    g_lstd[go * 3 + 2] = (float)sqrt(czz > 0.0 ? czz : 0.0);

    // deterministic fixed-point (2^40) sum: warp -> block -> one atomic
    unsigned long long sc = (unsigned long long)llrint(curv * 1099511627776.0);
#pragma unroll
    for (int o = 16; o; o >>= 1)
        sc += __shfl_xor_sync(0xffffffffu, sc, o);
    int lane = threadIdx.x & 31, wi = threadIdx.x >> 5;
    if (lane == 0) wsum[wi] = sc;
    __syncthreads();
    if (threadIdx.x == 0) {
        unsigned long long t = 0;
        for (int w = 0; w < 8; w++) t += wsum[w];
        atomicAdd(&g_curvsum[b], t);
    }
}

// ============================================================
// Kernel 6: embedding via geometric/rotation recurrences
// ============================================================
__global__ void __launch_bounds__(96)
embed_kernel(const float* __restrict__ xyz, float* __restrict__ out) {
    __shared__ float sm[32][129];
    int tid = threadIdx.x;
    int p = tid & 31;
    int d = tid >> 5;
    int b = blockIdx.y;
    int n0 = blockIdx.x * 32;
    int gp = b * NPTS + n0 + p;

    float x    = xyz[(size_t)gp * 3 + d];
    float lstd = g_lstd[(size_t)gp * 3 + d];
    float curv = g_curv[gp];
    float cm   = (float)((double)(long long)g_curvsum[b]
                         * (1.0 / 1099511627776.0) * (1.0 / 4096.0));
    float w    = 1.0f / (1.0f + __expf(-10.0f * (curv - cm)));

    float invS1 = g_scal[1], blend = g_scal[2];
    float Q1 = g_scal[3], cd1 = g_scal[4], sd1 = g_scal[5], d1 = g_scal[6];

    float Aw = w * blend;
    float Bw = w * (1.0f - blend);
    float Cw = 1.0f - w;

    const float h   = 0.045454545454545456f;   // 1/22
    const float fv0 = -0.9545454545454546f;    // FEAT_VAL[0]

    float S2   = fmaf(0.3f, lstd, 0.3f) + 1e-6f;
    float inv2 = 1.0f / S2;
    float d2s  = h * inv2;
    float Q2   = __expf(-d2s * d2s);

    bool  up  = (x <= 0.0f);
    float sgn = up ? 1.0f : -1.0f;
    int   f   = up ? 0 : 42;
    int   df  = up ? 1 : -1;
    float fva = up ? fv0 : -fv0;

    float t1 = (x - fva) * invS1;
    float t2 = (x - fva) * inv2;
    float G1 = __expf(-0.5f * t1 * t1);
    float G2 = __expf(-0.5f * t2 * t2);
    float r1 = __expf(sgn * d1  * (t1 - sgn * 0.5f * d1));
    float r2 = __expf(sgn * d2s * (t2 - sgn * 0.5f * d2s));
    float cc = __cosf(t1);
    float sn = __sinf(t1);
    float sd = up ? sd1 : -sd1;

    for (int it = 0; it < 43; it++) {
        float val = fmaf(Aw, G1, fmaf(Bw, cc, Cw * G2));
        int col;
        if (d < 2) col = d * 43 + f;
        else       col = (f < 41) ? (86 + f) : ((f == 42) ? 127 : -1);
        if (col >= 0) sm[p][col] = val;
        G1 *= r1; r1 *= Q1;
        G2 *= r2; r2 *= Q2;
        float cn  = fmaf(cc, cd1,  sn * sd);
        float sn2 = fmaf(sn, cd1, -cc * sd);
        cc = cn; sn = sn2;
        f += df;
    }
    __syncthreads();

    float* ob = out + ((size_t)b * NPTS + n0) * 128;
    for (int i = tid; i < 32 * 128; i += 96)
        ob[i] = sm[i >> 7][i & 127];
}

// ============================================================
extern "C" void kernel_launch(void* const* d_in, const int* in_sizes, int n_in,
                              void* d_out, int out_size) {
    const float* xyz = (const float*)d_in[0];
    float* out = (float*)d_out;
    (void)in_sizes; (void)n_in; (void)out_size;

    const int knn_smem = 3 * NTOT * 4;   // 49920 B -> 4 blocks/SM
    cudaFuncSetAttribute(knn_kernel, cudaFuncAttributeMaxDynamicSharedMemorySize, knn_smem);

    bd_std_kernel<<<24, 256>>>(xyz);
    consts_kernel<<<1, 32>>>();
    sort_kernel<<<NB, 1024>>>(xyz);
    dim3 kg(NPTS / 64, NB);              // 64 x 8 = 512 blocks, single wave at 4/SM
    knn_kernel<<<kg, BT, knn_smem>>>();
    dim3 eg2(NPTS / 256, NB);
    eigen_kernel<<<eg2, 256>>>();
    dim3 eg(NPTS / 32, NB);
    embed_kernel<<<eg, 96>>>(xyz, out);
}